// round 1
// baseline (speedup 1.0000x reference)
#include <cuda_runtime.h>
#include <cuda_bf16.h>

#define NUM_USERS 200000
#define NUM_ITEMS 100000
#define NUM_NODES (NUM_USERS + NUM_ITEMS)
#define NUM_EDGES 600000
#define DIM 128
#define BATCH 16384
#define GPB 32              // pairs per block in the pair kernel

// ---------------- scratch (static device globals; no runtime allocation) ----
__device__ __align__(16) float g_agg[(size_t)NUM_NODES * DIM];   // masked segment-sum
__device__ __align__(16) unsigned char g_mask[NUM_NODES];        // needed-node mask
__device__ __align__(16) int2 g_queue[NUM_EDGES];                // compacted edges
__device__ int g_qcount;
__device__ __align__(16) float g_M[DIM * DIM];                   // W^T W
__device__ __align__(16) float g_v[DIM];                         // W^T b
__device__ float g_c;                                            // b.b

// ---------------- K0a: M = W^T W -------------------------------------------
__global__ void k_precompute_M(const float* __restrict__ W) {
    int r = blockIdx.x;      // 0..127
    int c = threadIdx.x;     // 0..127
    float acc = 0.f;
#pragma unroll 8
    for (int j = 0; j < DIM; j++)
        acc += W[j * DIM + r] * W[j * DIM + c];
    g_M[r * DIM + c] = acc;
}

// ---------------- K0b: v = W^T b, c = b.b -----------------------------------
__global__ void k_precompute_v(const float* __restrict__ W, const float* __restrict__ b) {
    int c = threadIdx.x;     // 0..127
    float acc = 0.f;
#pragma unroll 8
    for (int j = 0; j < DIM; j++)
        acc += b[j] * W[j * DIM + c];
    g_v[c] = acc;
    if (c == 0) {
        float s = 0.f;
#pragma unroll 8
        for (int j = 0; j < DIM; j++) s += b[j] * b[j];
        g_c = s;
    }
}

// ---------------- K1: zero mask + queue counter -----------------------------
__global__ void k_reset() {
    int i = blockIdx.x * blockDim.x + threadIdx.x;
    const int n16 = NUM_NODES / 16;      // 18750, exact
    if (i < n16) ((int4*)g_mask)[i] = make_int4(0, 0, 0, 0);
    if (i == 0) g_qcount = 0;
}

// ---------------- K2: mark needed nodes, zero their agg rows -----------------
__global__ void k_mark_zero(const int* __restrict__ ui, const int* __restrict__ ii) {
    int t = blockIdx.x * blockDim.x + threadIdx.x;    // 2*BATCH*32 threads
    int ref = t >> 5;
    int sub = t & 31;
    if (ref >= 2 * BATCH) return;
    int node = (ref < BATCH) ? ui[ref] : (NUM_USERS + ii[ref - BATCH]);
    ((float4*)(g_agg + (size_t)node * DIM))[sub] = make_float4(0.f, 0.f, 0.f, 0.f);
    if (sub == 0) g_mask[node] = 1;
}

// ---------------- K3a: compact passing edges into queue ---------------------
__global__ void k_compact(const int* __restrict__ src, const int* __restrict__ dst) {
    __shared__ int wcnt[16], wbase[16], bbase;
    int e = blockIdx.x * blockDim.x + threadIdx.x;
    bool pass = false;
    int d = 0;
    if (e < NUM_EDGES) {
        d = dst[e];
        pass = (g_mask[d] != 0);
    }
    unsigned m = __ballot_sync(0xffffffffu, pass);
    int warp = threadIdx.x >> 5, lane = threadIdx.x & 31;
    if (lane == 0) wcnt[warp] = __popc(m);
    __syncthreads();
    if (threadIdx.x == 0) {
        int tot = 0;
#pragma unroll
        for (int w = 0; w < 16; w++) { wbase[w] = tot; tot += wcnt[w]; }
        bbase = atomicAdd(&g_qcount, tot);
    }
    __syncthreads();
    if (pass) {
        int s = src[e];
        int pos = bbase + wbase[warp] + __popc(m & ((1u << lane) - 1));
        g_queue[pos] = make_int2(s, d);
    }
}

// ---------------- K3b: masked scatter-add (warp per queued edge) ------------
__global__ void k_scatter(const float* __restrict__ uemb, const float* __restrict__ iemb) {
    int q = g_qcount;
    int gw = (blockIdx.x * blockDim.x + threadIdx.x) >> 5;
    int lane = threadIdx.x & 31;
    int nw = (gridDim.x * blockDim.x) >> 5;
    for (int i = gw; i < q; i += nw) {
        int2 e = g_queue[i];
        const float* sp = (e.x < NUM_USERS)
                            ? (uemb + (size_t)e.x * DIM)
                            : (iemb + (size_t)(e.x - NUM_USERS) * DIM);
        float4 v = ((const float4*)sp)[lane];
        float* a = g_agg + (size_t)e.y * DIM + lane * 4;
        atomicAdd(a + 0, v.x);
        atomicAdd(a + 1, v.y);
        atomicAdd(a + 2, v.z);
        atomicAdd(a + 3, v.w);
    }
}

// ---------------- K4: out[p] = xu^T M xi + v.xu + v.xi + c -------------------
// 128 threads, GPB pairs per block. M staged in smem (padded stride 132 floats
// -> conflict-free LDS.128). f32x2 packed FMA for dual-rate fp32.
#define MS_STRIDE 132
#define SMEM_K4 ((DIM * MS_STRIDE + GPB * DIM + DIM + GPB * 4) * 4 + GPB * 2 * 4)

__global__ void __launch_bounds__(128) k_pairs(
    const int* __restrict__ ui, const int* __restrict__ ii,
    float* __restrict__ out)
{
    extern __shared__ float sm[];
    float* Ms   = sm;                               // DIM * MS_STRIDE
    float* Xi   = Ms + DIM * MS_STRIDE;             // GPB * DIM
    float* Vv   = Xi + GPB * DIM;                   // DIM
    float* Wsum = Vv + DIM;                         // GPB * 4
    int*   Nd   = (int*)(Wsum + GPB * 4);           // 2*GPB ints: user nodes, item nodes

    int tid = threadIdx.x;
    int base = blockIdx.x * GPB;

    // stage M (padded), v, node ids
    for (int idx = tid; idx < DIM * DIM; idx += 128) {
        int r = idx >> 7, c = idx & 127;
        Ms[r * MS_STRIDE + c] = g_M[idx];
    }
    if (tid < DIM) Vv[tid] = g_v[tid];
    if (tid < GPB) {
        Nd[tid]       = ui[base + tid];
        Nd[GPB + tid] = NUM_USERS + ii[base + tid];
    }
    __syncthreads();

    // stage Xi rows (item-side agg) into smem
    for (int idx = tid; idx < GPB * (DIM / 4); idx += 128) {
        int g = idx >> 5, k4 = idx & 31;
        ((float4*)(Xi + g * DIM))[k4] =
            ((const float4*)(g_agg + (size_t)Nd[GPB + g] * DIM))[k4];
    }
    __syncthreads();

    // y[g][tid] = sum_k Ms[tid][k] * Xi[g][k]   (f32x2 packed accumulate)
    unsigned long long acc[GPB];
#pragma unroll
    for (int g = 0; g < GPB; g++) acc[g] = 0ull;

    const ulonglong2* mrow = (const ulonglong2*)(Ms + tid * MS_STRIDE);
    for (int k4 = 0; k4 < DIM / 4; k4++) {
        ulonglong2 m2 = mrow[k4];                    // 4 M values, packed as 2x f32x2
#pragma unroll
        for (int g = 0; g < GPB; g++) {
            ulonglong2 x2 = ((const ulonglong2*)(Xi + g * DIM))[k4];  // broadcast LDS.128
            asm("fma.rn.f32x2 %0, %1, %2, %0;" : "+l"(acc[g]) : "l"(m2.x), "l"(x2.x));
            asm("fma.rn.f32x2 %0, %1, %2, %0;" : "+l"(acc[g]) : "l"(m2.y), "l"(x2.y));
        }
    }

    // finalize: t_j = xu_j*(y_j + v_j) + v_j*xi_j ; block-reduce per pair
    float vj = Vv[tid];
    int lane = tid & 31, warp = tid >> 5;
#pragma unroll
    for (int g = 0; g < GPB; g++) {
        float lo, hi;
        asm("mov.b64 {%0, %1}, %2;" : "=f"(lo), "=f"(hi) : "l"(acc[g]));
        float y  = lo + hi;
        float xu = g_agg[(size_t)Nd[g] * DIM + tid];   // coalesced
        float xi = Xi[g * DIM + tid];
        float t  = xu * (y + vj) + vj * xi;
#pragma unroll
        for (int off = 16; off; off >>= 1)
            t += __shfl_xor_sync(0xffffffffu, t, off);
        if (lane == 0) Wsum[g * 4 + warp] = t;
    }
    __syncthreads();
    if (tid < GPB) {
        float s = Wsum[tid * 4 + 0] + Wsum[tid * 4 + 1]
                + Wsum[tid * 4 + 2] + Wsum[tid * 4 + 3] + g_c;
        out[base + tid] = s;
    }
}

// ---------------- launch ----------------------------------------------------
extern "C" void kernel_launch(void* const* d_in, const int* in_sizes, int n_in,
                              void* d_out, int out_size) {
    const int*   ui   = (const int*)d_in[0];
    const int*   ii   = (const int*)d_in[1];
    const float* uemb = (const float*)d_in[2];
    const float* iemb = (const float*)d_in[3];
    const float* W    = (const float*)d_in[4];
    const float* b    = (const float*)d_in[5];
    const int*   ei   = (const int*)d_in[6];
    const int*   src  = ei;
    const int*   dst  = ei + NUM_EDGES;
    float*       out  = (float*)d_out;

    cudaFuncSetAttribute(k_pairs, cudaFuncAttributeMaxDynamicSharedMemorySize, SMEM_K4);

    k_precompute_M<<<DIM, DIM>>>(W);
    k_precompute_v<<<1, DIM>>>(W, b);
    k_reset<<<(NUM_NODES / 16 + 255) / 256, 256>>>();
    k_mark_zero<<<(2 * BATCH * 32) / 256, 256>>>(ui, ii);
    k_compact<<<(NUM_EDGES + 511) / 512, 512>>>(src, dst);
    k_scatter<<<1184, 256>>>(uemb, iemb);
    k_pairs<<<BATCH / GPB, 128, SMEM_K4>>>(ui, ii, out);
}

// round 2
// speedup vs baseline: 1.2671x; 1.2671x over previous
#include <cuda_runtime.h>
#include <cuda_bf16.h>

#define NUM_USERS 200000
#define NUM_ITEMS 100000
#define NUM_NODES (NUM_USERS + NUM_ITEMS)
#define NUM_EDGES 600000
#define DIM 128
#define BATCH 16384
#define GPB 32              // pairs per block in the pair kernel

// ---------------- scratch (static device globals; no runtime allocation) ----
__device__ __align__(16) float g_agg[(size_t)NUM_NODES * DIM];   // masked segment-sum
__device__ __align__(16) unsigned char g_mask[NUM_NODES];        // needed-node mask
__device__ __align__(16) float g_M[DIM * DIM];                   // W^T W
__device__ __align__(16) float g_v[DIM];                         // W^T b
__device__ float g_c;                                            // b.b

// ---------------- K0 (fused): M = W^T W, v = W^T b, c = b.b, mask = 0 -------
// blocks [0, DIM): row r of M (block 0 also does v and c)
// blocks [DIM, DIM+74): zero the mask (2 x int4 per thread)
#define MASK16 (NUM_NODES / 16)                 // 18750 int4 slots, exact
#define ZBLOCKS ((MASK16 + 255) / 256)          // 74
__global__ void k_pre(const float* __restrict__ W, const float* __restrict__ b) {
    int blk = blockIdx.x;
    int tid = threadIdx.x;
    if (blk < DIM) {
        int r = blk, c = tid;
        float acc = 0.f;
#pragma unroll 8
        for (int j = 0; j < DIM; j++)
            acc += W[j * DIM + r] * W[j * DIM + c];
        g_M[r * DIM + c] = acc;
        if (blk == 0) {
            float vv = 0.f;
#pragma unroll 8
            for (int j = 0; j < DIM; j++) vv += b[j] * W[j * DIM + c];
            g_v[c] = vv;
            if (tid == 0) {
                float s = 0.f;
#pragma unroll 8
                for (int j = 0; j < DIM; j++) s += b[j] * b[j];
                g_c = s;
            }
        }
    } else {
        int i0 = (blk - DIM) * 256 + tid;
        if (i0 < MASK16) ((int4*)g_mask)[i0] = make_int4(0, 0, 0, 0);
        int i1 = i0 + 128;
        if (i1 < MASK16) ((int4*)g_mask)[i1] = make_int4(0, 0, 0, 0);
    }
}

// ---------------- K1: mark needed nodes, zero their agg rows -----------------
__global__ void k_mark_zero(const int* __restrict__ ui, const int* __restrict__ ii) {
    int t = blockIdx.x * blockDim.x + threadIdx.x;    // 2*BATCH*32 threads
    int ref = t >> 5;
    int sub = t & 31;
    if (ref >= 2 * BATCH) return;
    int node = (ref < BATCH) ? ui[ref] : (NUM_USERS + ii[ref - BATCH]);
    ((float4*)(g_agg + (size_t)node * DIM))[sub] = make_float4(0.f, 0.f, 0.f, 0.f);
    if (sub == 0) g_mask[node] = 1;
}

// ---------------- K2 (fused): scan edges, gather + vectorized scatter-add ----
// Each warp scans 32 contiguous edges (coalesced dst read + mask probe),
// ballots on the mask, then the full warp handles each passing edge:
// 512B coalesced gather + one red.global.add.v4.f32 per lane (RED.128).
__global__ void k_edge(const int* __restrict__ src, const int* __restrict__ dst,
                       const float* __restrict__ uemb, const float* __restrict__ iemb) {
    int e = blockIdx.x * blockDim.x + threadIdx.x;
    int lane = threadIdx.x & 31;
    bool pass = false;
    int d = 0, s = 0;
    if (e < NUM_EDGES) {
        d = dst[e];
        pass = (g_mask[d] != 0);
        if (pass) s = src[e];          // predicated, near-coalesced within warp
    }
    unsigned m = __ballot_sync(0xffffffffu, pass);
    while (m) {
        int bit = __ffs(m) - 1;
        m &= m - 1;
        int ds = __shfl_sync(0xffffffffu, d, bit);
        int ss = __shfl_sync(0xffffffffu, s, bit);
        const float* sp = (ss < NUM_USERS)
                            ? (uemb + (size_t)ss * DIM)
                            : (iemb + (size_t)(ss - NUM_USERS) * DIM);
        float4 v = ((const float4*)sp)[lane];
        float* a = g_agg + (size_t)ds * DIM + lane * 4;
        asm volatile("red.global.add.v4.f32 [%0], {%1, %2, %3, %4};"
                     :: "l"(a), "f"(v.x), "f"(v.y), "f"(v.z), "f"(v.w)
                     : "memory");
    }
}

// ---------------- K3: out[p] = xu^T M xi + v.xu + v.xi + c -------------------
// 128 threads, GPB pairs per block. M staged in smem (padded stride 132 floats
// -> conflict-free LDS.128). f32x2 packed FMA for dual-rate fp32.
#define MS_STRIDE 132
#define SMEM_K4 ((DIM * MS_STRIDE + GPB * DIM + DIM + GPB * 4) * 4 + GPB * 2 * 4)

__global__ void __launch_bounds__(128) k_pairs(
    const int* __restrict__ ui, const int* __restrict__ ii,
    float* __restrict__ out)
{
    extern __shared__ float sm[];
    float* Ms   = sm;                               // DIM * MS_STRIDE
    float* Xi   = Ms + DIM * MS_STRIDE;             // GPB * DIM
    float* Vv   = Xi + GPB * DIM;                   // DIM
    float* Wsum = Vv + DIM;                         // GPB * 4
    int*   Nd   = (int*)(Wsum + GPB * 4);           // 2*GPB ints: user nodes, item nodes

    int tid = threadIdx.x;
    int base = blockIdx.x * GPB;

    // stage M (padded), v, node ids
    for (int idx = tid; idx < DIM * DIM; idx += 128) {
        int r = idx >> 7, c = idx & 127;
        Ms[r * MS_STRIDE + c] = g_M[idx];
    }
    if (tid < DIM) Vv[tid] = g_v[tid];
    if (tid < GPB) {
        Nd[tid]       = ui[base + tid];
        Nd[GPB + tid] = NUM_USERS + ii[base + tid];
    }
    __syncthreads();

    // stage Xi rows (item-side agg) into smem
    for (int idx = tid; idx < GPB * (DIM / 4); idx += 128) {
        int g = idx >> 5, k4 = idx & 31;
        ((float4*)(Xi + g * DIM))[k4] =
            ((const float4*)(g_agg + (size_t)Nd[GPB + g] * DIM))[k4];
    }
    __syncthreads();

    // y[g][tid] = sum_k Ms[tid][k] * Xi[g][k]   (f32x2 packed accumulate)
    unsigned long long acc[GPB];
#pragma unroll
    for (int g = 0; g < GPB; g++) acc[g] = 0ull;

    const ulonglong2* mrow = (const ulonglong2*)(Ms + tid * MS_STRIDE);
    for (int k4 = 0; k4 < DIM / 4; k4++) {
        ulonglong2 m2 = mrow[k4];                    // 4 M values, packed as 2x f32x2
#pragma unroll
        for (int g = 0; g < GPB; g++) {
            ulonglong2 x2 = ((const ulonglong2*)(Xi + g * DIM))[k4];  // broadcast LDS.128
            asm("fma.rn.f32x2 %0, %1, %2, %0;" : "+l"(acc[g]) : "l"(m2.x), "l"(x2.x));
            asm("fma.rn.f32x2 %0, %1, %2, %0;" : "+l"(acc[g]) : "l"(m2.y), "l"(x2.y));
        }
    }

    // finalize: t_j = xu_j*(y_j + v_j) + v_j*xi_j ; block-reduce per pair
    float vj = Vv[tid];
    int lane = tid & 31, warp = tid >> 5;
#pragma unroll
    for (int g = 0; g < GPB; g++) {
        float lo, hi;
        asm("mov.b64 {%0, %1}, %2;" : "=f"(lo), "=f"(hi) : "l"(acc[g]));
        float y  = lo + hi;
        float xu = g_agg[(size_t)Nd[g] * DIM + tid];   // coalesced
        float xi = Xi[g * DIM + tid];
        float t  = xu * (y + vj) + vj * xi;
#pragma unroll
        for (int off = 16; off; off >>= 1)
            t += __shfl_xor_sync(0xffffffffu, t, off);
        if (lane == 0) Wsum[g * 4 + warp] = t;
    }
    __syncthreads();
    if (tid < GPB) {
        float s = Wsum[tid * 4 + 0] + Wsum[tid * 4 + 1]
                + Wsum[tid * 4 + 2] + Wsum[tid * 4 + 3] + g_c;
        out[base + tid] = s;
    }
}

// ---------------- launch ----------------------------------------------------
extern "C" void kernel_launch(void* const* d_in, const int* in_sizes, int n_in,
                              void* d_out, int out_size) {
    const int*   ui   = (const int*)d_in[0];
    const int*   ii   = (const int*)d_in[1];
    const float* uemb = (const float*)d_in[2];
    const float* iemb = (const float*)d_in[3];
    const float* W    = (const float*)d_in[4];
    const float* b    = (const float*)d_in[5];
    const int*   ei   = (const int*)d_in[6];
    const int*   src  = ei;
    const int*   dst  = ei + NUM_EDGES;
    float*       out  = (float*)d_out;

    cudaFuncSetAttribute(k_pairs, cudaFuncAttributeMaxDynamicSharedMemorySize, SMEM_K4);

    k_pre<<<DIM + ZBLOCKS, DIM>>>(W, b);
    k_mark_zero<<<(2 * BATCH * 32) / 256, 256>>>(ui, ii);
    k_edge<<<(NUM_EDGES + 255) / 256, 256>>>(src, dst, uemb, iemb);
    k_pairs<<<BATCH / GPB, 128, SMEM_K4>>>(ui, ii, out);
}

// round 4
// speedup vs baseline: 2.2488x; 1.7747x over previous
#include <cuda_runtime.h>
#include <cuda_bf16.h>

#define NUM_USERS 200000
#define NUM_ITEMS 100000
#define NUM_NODES (NUM_USERS + NUM_ITEMS)
#define NUM_EDGES 600000
#define DIM 128
#define BATCH 16384

// ---------------- scratch (static device globals; no runtime allocation) ----
__device__ __align__(16) float g_agg[(size_t)NUM_NODES * DIM];   // masked segment-sum
__device__ __align__(16) unsigned char g_mask[NUM_NODES];        // needed-node mask
__device__ __align__(16) float g_M[DIM * DIM];                   // W^T W (symmetric!)
__device__ __align__(16) float g_v[DIM];                         // W^T b
__device__ float g_c;                                            // b.b

// ---------------- f32x2 helpers ---------------------------------------------
__device__ __forceinline__ unsigned long long pack2(float x, float y) {
    unsigned long long r;
    asm("mov.b64 %0, {%1, %2};" : "=l"(r) : "f"(x), "f"(y));
    return r;
}
__device__ __forceinline__ void fma2(unsigned long long& acc,
                                     unsigned long long a, unsigned long long b) {
    asm("fma.rn.f32x2 %0, %1, %2, %0;" : "+l"(acc) : "l"(a), "l"(b));
}
__device__ __forceinline__ void unpack2(unsigned long long v, float& lo, float& hi) {
    asm("mov.b64 {%0, %1}, %2;" : "=f"(lo), "=f"(hi) : "l"(v));
}

// ---------------- K0 (fused): M = W^T W, v = W^T b, c = b.b, mask = 0 -------
#define MASK16 (NUM_NODES / 16)                 // 18750 int4 slots, exact
#define ZBLOCKS ((MASK16 + 255) / 256)          // 74
__global__ void k_pre(const float* __restrict__ W, const float* __restrict__ b) {
    int blk = blockIdx.x;
    int tid = threadIdx.x;
    if (blk < DIM) {
        int r = blk, c = tid;
        float acc = 0.f;
#pragma unroll 8
        for (int j = 0; j < DIM; j++)
            acc += W[j * DIM + r] * W[j * DIM + c];
        g_M[r * DIM + c] = acc;
        if (blk == 0) {
            float vv = 0.f;
#pragma unroll 8
            for (int j = 0; j < DIM; j++) vv += b[j] * W[j * DIM + c];
            g_v[c] = vv;
            if (tid == 0) {
                float s = 0.f;
#pragma unroll 8
                for (int j = 0; j < DIM; j++) s += b[j] * b[j];
                g_c = s;
            }
        }
    } else {
        int i0 = (blk - DIM) * 256 + tid;
        if (i0 < MASK16) ((int4*)g_mask)[i0] = make_int4(0, 0, 0, 0);
        int i1 = i0 + 128;
        if (i1 < MASK16) ((int4*)g_mask)[i1] = make_int4(0, 0, 0, 0);
    }
}

// ---------------- K1: mark needed nodes, zero their agg rows -----------------
__global__ void k_mark_zero(const int* __restrict__ ui, const int* __restrict__ ii) {
    int t = blockIdx.x * blockDim.x + threadIdx.x;    // 2*BATCH*32 threads
    int ref = t >> 5;
    int sub = t & 31;
    if (ref >= 2 * BATCH) return;
    int node = (ref < BATCH) ? ui[ref] : (NUM_USERS + ii[ref - BATCH]);
    ((float4*)(g_agg + (size_t)node * DIM))[sub] = make_float4(0.f, 0.f, 0.f, 0.f);
    if (sub == 0) g_mask[node] = 1;
}

// ---------------- K2 (fused): scan edges, gather + vectorized scatter-add ----
__global__ void k_edge(const int* __restrict__ src, const int* __restrict__ dst,
                       const float* __restrict__ uemb, const float* __restrict__ iemb) {
    int e = blockIdx.x * blockDim.x + threadIdx.x;
    int lane = threadIdx.x & 31;
    bool pass = false;
    int d = 0, s = 0;
    if (e < NUM_EDGES) {
        d = dst[e];
        pass = (g_mask[d] != 0);
        if (pass) s = src[e];
    }
    unsigned m = __ballot_sync(0xffffffffu, pass);
    while (m) {
        int bit = __ffs(m) - 1;
        m &= m - 1;
        int ds = __shfl_sync(0xffffffffu, d, bit);
        int ss = __shfl_sync(0xffffffffu, s, bit);
        const float* sp = (ss < NUM_USERS)
                            ? (uemb + (size_t)ss * DIM)
                            : (iemb + (size_t)(ss - NUM_USERS) * DIM);
        float4 v = ((const float4*)sp)[lane];
        float* a = g_agg + (size_t)ds * DIM + lane * 4;
        asm volatile("red.global.add.v4.f32 [%0], {%1, %2, %3, %4};"
                     :: "l"(a), "f"(v.x), "f"(v.y), "f"(v.z), "f"(v.w)
                     : "memory");
    }
}

// ---------------- K3: register-tiled fused GEMM + bilinear reduce ------------
// Block: 128 pairs x 128 cols, 256 threads, 8x8 register tile per thread.
// Y = XI @ M^T (M symmetric -> Ms[k][j] = g_M row copy, no transpose).
// v.xi folded into the main k-loop via packed FMA on the a-fragment.
// out[i] = sum_j [ xu[i,j]*(y[i,j]+v[j]) ] + v.xi_i + b.b
#define BPB 128
#define PADI 130   // even: 8B-aligned float2/u64 a-frag loads; 2-way STS conflict only
#define SMEM_K3 ((DIM * DIM + DIM * PADI + DIM) * 4 + DIM * 4)

__global__ void __launch_bounds__(256) k_pairs(
    const int* __restrict__ ui, const int* __restrict__ ii,
    float* __restrict__ out)
{
    extern __shared__ float sm[];
    float* Ms  = sm;                       // [128][128]  k-major (M symmetric)
    float* XIs = Ms + DIM * DIM;           // [128][PADI] XIs[k*PADI + i]
    float* Vv  = XIs + DIM * PADI;         // [128]
    int*   Nd  = (int*)(Vv + DIM);         // [128] user node ids

    int tid  = threadIdx.x;
    int base = blockIdx.x * BPB;
    int warp = tid >> 5, lane = tid & 31;

    // stage M: straight coalesced float4 copy (symmetric => already [k][j])
    for (int idx = tid; idx < DIM * DIM / 4; idx += 256)
        ((float4*)Ms)[idx] = ((const float4*)g_M)[idx];
    if (tid < DIM) { Vv[tid] = g_v[tid]; Nd[tid] = ui[base + tid]; }

    // stage XI transposed: warp w handles rows [w*16, w*16+16).
    // lane loads k = lane + 32c (4 coalesced 128B scalar LDGs per row);
    // STS bank = (2*lane)%32 -> 2-way conflict.
    for (int r = 0; r < 16; r++) {
        int g = warp * 16 + r;
        int node = NUM_USERS + __ldg(&ii[base + g]);
        const float* rowp = g_agg + (size_t)node * DIM + lane;
#pragma unroll
        for (int c = 0; c < 4; c++)
            XIs[(lane + 32 * c) * PADI + g] = rowp[32 * c];
    }
    __syncthreads();

    int tx = tid & 15, ty = tid >> 4;
    int j0 = tx * 8, i0 = ty * 8;

    unsigned long long acc[8][4];
    unsigned long long vacc[4];
#pragma unroll
    for (int i = 0; i < 8; i++)
#pragma unroll
        for (int jp = 0; jp < 4; jp++) acc[i][jp] = 0ull;
#pragma unroll
    for (int t = 0; t < 4; t++) vacc[t] = 0ull;

#pragma unroll 4
    for (int k = 0; k < DIM; k++) {
        // a-fragment: 8 xi values for pairs i0..i0+7 (four 8B loads, broadcast)
        unsigned long long au[4];
#pragma unroll
        for (int t = 0; t < 4; t++)
            au[t] = *(const unsigned long long*)&XIs[k * PADI + i0 + 2 * t];
        // b-fragment: 8 M values (two 16B loads)
        ulonglong2 b0 = *(const ulonglong2*)&Ms[k * DIM + j0];
        ulonglong2 b1 = *(const ulonglong2*)&Ms[k * DIM + j0 + 4];

        // fold v.xi: vacc[t] += (v[k],v[k]) * (xi[2t],xi[2t+1])
        float vk = Vv[k];
        unsigned long long vkd = pack2(vk, vk);
#pragma unroll
        for (int t = 0; t < 4; t++) fma2(vacc[t], au[t], vkd);

        float av[8];
#pragma unroll
        for (int t = 0; t < 4; t++) unpack2(au[t], av[2 * t], av[2 * t + 1]);
#pragma unroll
        for (int i = 0; i < 8; i++) {
            unsigned long long ad = pack2(av[i], av[i]);
            fma2(acc[i][0], ad, b0.x);
            fma2(acc[i][1], ad, b0.y);
            fma2(acc[i][2], ad, b1.x);
            fma2(acc[i][3], ad, b1.y);
        }
    }

    // epilogue: p_i(tx) = sum_{q in tile} xu[i][j0+q]*(y+v)[j0+q]; reduce over tx
    float vj[8];
#pragma unroll
    for (int q = 0; q < 8; q++) vj[q] = Vv[j0 + q];

    float cc = g_c;
#pragma unroll
    for (int r = 0; r < 8; r++) {
        int i = i0 + r;
        const float* xup = g_agg + (size_t)Nd[i] * DIM + j0;
        float4 xu0 = *(const float4*)xup;
        float4 xu1 = *(const float4*)(xup + 4);
        float xuv[8] = {xu0.x, xu0.y, xu0.z, xu0.w, xu1.x, xu1.y, xu1.z, xu1.w};
        float y[8];
#pragma unroll
        for (int jp = 0; jp < 4; jp++) unpack2(acc[r][jp], y[2 * jp], y[2 * jp + 1]);
        float p = 0.f;
#pragma unroll
        for (int q = 0; q < 8; q++)
            p += xuv[q] * (y[q] + vj[q]);
#pragma unroll
        for (int off = 1; off < 16; off <<= 1)
            p += __shfl_xor_sync(0xffffffffu, p, off);
        if (tx == 0) {
            float d0, d1;
            unpack2(vacc[r >> 1], d0, d1);
            float vdot = (r & 1) ? d1 : d0;
            out[base + i] = p + vdot + cc;
        }
    }
}

// ---------------- launch ----------------------------------------------------
extern "C" void kernel_launch(void* const* d_in, const int* in_sizes, int n_in,
                              void* d_out, int out_size) {
    const int*   ui   = (const int*)d_in[0];
    const int*   ii   = (const int*)d_in[1];
    const float* uemb = (const float*)d_in[2];
    const float* iemb = (const float*)d_in[3];
    const float* W    = (const float*)d_in[4];
    const float* b    = (const float*)d_in[5];
    const int*   ei   = (const int*)d_in[6];
    const int*   src  = ei;
    const int*   dst  = ei + NUM_EDGES;
    float*       out  = (float*)d_out;

    cudaFuncSetAttribute(k_pairs, cudaFuncAttributeMaxDynamicSharedMemorySize, SMEM_K3);

    k_pre<<<DIM + ZBLOCKS, DIM>>>(W, b);
    k_mark_zero<<<(2 * BATCH * 32) / 256, 256>>>(ui, ii);
    k_edge<<<(NUM_EDGES + 255) / 256, 256>>>(src, dst, uemb, iemb);
    k_pairs<<<BATCH / BPB, 256, SMEM_K3>>>(ui, ii, out);
}